// round 13
// baseline (speedup 1.0000x reference)
#include <cuda_runtime.h>
#include <cuda_bf16.h>
#include <mma.h>
#include <math.h>
#include <stdint.h>

using namespace nvcuda;

#define NN 8192
#define KNB 16
#define DD 256
#define EE 128
#define HH 512
#define OO 256

// ---- scratch (no allocations allowed; __device__ globals) ----
__device__ float g_yn[NN * HH];
__device__ float g_ye[NN * HH];
__device__ float g_wsn[NN * KNB];
__device__ float g_wse[NN * KNB];
__device__ float g_aggn[NN * DD];
__device__ float g_agge[NN * EE];
// bf16 hi/lo splits: ws inputs
__device__ __nv_bfloat16 g_nhi[NN * KNB * DD];
__device__ __nv_bfloat16 g_nlo[NN * KNB * DD];
__device__ __nv_bfloat16 g_ehi[NN * KNB * EE];
__device__ __nv_bfloat16 g_elo[NN * KNB * EE];
__device__ __nv_bfloat16 g_w1nhi[HH * DD];
__device__ __nv_bfloat16 g_w1nlo[HH * DD];
__device__ __nv_bfloat16 g_w1ehi[HH * EE];
__device__ __nv_bfloat16 g_w1elo[HH * EE];
// chain inputs/activations (hi/lo)
__device__ __nv_bfloat16 g_xhi[NN * DD];
__device__ __nv_bfloat16 g_xlo[NN * DD];
__device__ __nv_bfloat16 g_h1hi[NN * HH];
__device__ __nv_bfloat16 g_h1lo[NN * HH];
__device__ __nv_bfloat16 g_xahi[NN * HH];
__device__ __nv_bfloat16 g_xalo[NN * HH];
__device__ __nv_bfloat16 g_anhi[NN * DD];
__device__ __nv_bfloat16 g_anlo[NN * DD];
__device__ __nv_bfloat16 g_aehi[NN * EE];
__device__ __nv_bfloat16 g_aelo[NN * EE];
// weight splits
__device__ __nv_bfloat16 g_w1xhi[HH * DD];
__device__ __nv_bfloat16 g_w1xlo[HH * DD];
__device__ __nv_bfloat16 g_w2xhi[HH * HH];
__device__ __nv_bfloat16 g_w2xlo[HH * HH];
__device__ __nv_bfloat16 g_w2nhi[HH * HH];
__device__ __nv_bfloat16 g_w2nlo[HH * HH];
__device__ __nv_bfloat16 g_w2ehi[HH * HH];
__device__ __nv_bfloat16 g_w2elo[HH * HH];
__device__ __nv_bfloat16 g_wfxhi[OO * DD];
__device__ __nv_bfloat16 g_wfxlo[OO * DD];
__device__ __nv_bfloat16 g_wfnhi[OO * DD];
__device__ __nv_bfloat16 g_wfnlo[OO * DD];
__device__ __nv_bfloat16 g_wfehi[OO * EE];
__device__ __nv_bfloat16 g_wfelo[OO * EE];

// ============================================================
// cp.async helpers
// ============================================================
__device__ __forceinline__ uint32_t smem_u32(const void* p) {
    uint32_t r;
    asm("{ .reg .u64 t; cvta.to.shared.u64 t, %1; cvt.u32.u64 %0, t; }"
        : "=r"(r) : "l"(p));
    return r;
}
#define CP16(dst_u32, src_ptr) \
    asm volatile("cp.async.cg.shared.global [%0], [%1], 16;" \
                 :: "r"(dst_u32), "l"(src_ptr) : "memory")
#define CP_COMMIT() asm volatile("cp.async.commit_group;" ::: "memory")
#define CP_WAIT1()  asm volatile("cp.async.wait_group 1;" ::: "memory")
#define CP_WAIT0()  asm volatile("cp.async.wait_group 0;" ::: "memory")

// ============================================================
// fp32 -> bf16 hi/lo split (elementwise, float4-vectorized)
// ============================================================
__global__ void __launch_bounds__(256)
split_kernel(const float* __restrict__ src, __nv_bfloat16* __restrict__ hi,
             __nv_bfloat16* __restrict__ lo, int n4)
{
    int i = blockIdx.x * blockDim.x + threadIdx.x;
    if (i >= n4) return;
    float4 v = ((const float4*)src)[i];
    __nv_bfloat162 h01 = __floats2bfloat162_rn(v.x, v.y);
    __nv_bfloat162 h23 = __floats2bfloat162_rn(v.z, v.w);
    float rx = v.x - __bfloat162float(h01.x);
    float ry = v.y - __bfloat162float(h01.y);
    float rz = v.z - __bfloat162float(h23.x);
    float rw = v.w - __bfloat162float(h23.y);
    __nv_bfloat162 l01 = __floats2bfloat162_rn(rx, ry);
    __nv_bfloat162 l23 = __floats2bfloat162_rn(rz, rw);
    uint2 ho, loo;
    ho.x  = *(uint32_t*)&h01; ho.y  = *(uint32_t*)&h23;
    loo.x = *(uint32_t*)&l01; loo.y = *(uint32_t*)&l23;
    ((uint2*)hi)[i] = ho;
    ((uint2*)lo)[i] = loo;
}

// ============================================================
// B-fragment handling for wgemm2 (unchanged from R11)
// ============================================================
template<bool BT> struct BFrag;
template<> struct BFrag<true> {
    using T = wmma::fragment<wmma::matrix_b, 16, 16, 16, __nv_bfloat16, wmma::col_major>;
    static __device__ __forceinline__ void load(T& f, const __nv_bfloat16* base,
                                                int n_idx, int ks) {
        wmma::load_matrix_sync(f, base + n_idx * 72 + ks * 16, 72);
    }
};
template<> struct BFrag<false> {
    using T = wmma::fragment<wmma::matrix_b, 16, 16, 16, __nv_bfloat16, wmma::row_major>;
    static __device__ __forceinline__ void load(T& f, const __nv_bfloat16* base,
                                                int n_idx, int ks) {
        wmma::load_matrix_sync(f, base + (ks * 16) * 136 + n_idx, 136);
    }
};

// ============================================================
// Generic WMMA GEMM (UNCHANGED from passing R11)
// ============================================================
#define WG2_SMEM 73728

template<bool BT, bool TANH_, bool BIASRELU_, bool SPLITOUT>
__global__ void __launch_bounds__(256, 2)
wgemm2(const __nv_bfloat16* __restrict__ Ahi, const __nv_bfloat16* __restrict__ Alo,
       const __nv_bfloat16* __restrict__ Bhi, const __nv_bfloat16* __restrict__ Blo,
       const float* __restrict__ bias,
       float* __restrict__ Cf, __nv_bfloat16* __restrict__ Chi, __nv_bfloat16* __restrict__ Clo,
       int Nc, int Kc, int ldc, int coff)
{
    extern __shared__ char sm[];
    __nv_bfloat16* As_hi = (__nv_bfloat16*)(sm);
    __nv_bfloat16* As_lo = (__nv_bfloat16*)(sm + 18432);
    __nv_bfloat16* Bs_hi = (__nv_bfloat16*)(sm + 36864);
    __nv_bfloat16* Bs_lo = (__nv_bfloat16*)(sm + 55296);
    float* Ds = (float*)sm;

    const int tid = threadIdx.x;
    const int wid = tid >> 5;
    const int m0 = blockIdx.y * 128;
    const int n0 = blockIdx.x * 128;
    const int m_off = (wid & 1) * 64;
    const int n_off = (wid >> 1) * 32;

    wmma::fragment<wmma::accumulator, 16, 16, 16, float> acc[4][2];
    #pragma unroll
    for (int mi = 0; mi < 4; mi++)
        #pragma unroll
        for (int ni = 0; ni < 2; ni++)
            wmma::fill_fragment(acc[mi][ni], 0.0f);

    const int KCH = Kc >> 6;
    for (int kc = 0; kc < KCH; kc++) {
        __syncthreads();
        #pragma unroll
        for (int i = 0; i < 4; i++) {
            int g = tid + i * 256;
            int row = g >> 3, c8 = (g & 7) * 8;
            size_t soff = (size_t)(m0 + row) * Kc + kc * 64 + c8;
            *(int4*)(As_hi + row * 72 + c8) = *(const int4*)(Ahi + soff);
            *(int4*)(As_lo + row * 72 + c8) = *(const int4*)(Alo + soff);
        }
        if (BT) {
            #pragma unroll
            for (int i = 0; i < 4; i++) {
                int g = tid + i * 256;
                int row = g >> 3, c8 = (g & 7) * 8;
                size_t soff = (size_t)(n0 + row) * Kc + kc * 64 + c8;
                *(int4*)(Bs_hi + row * 72 + c8) = *(const int4*)(Bhi + soff);
                *(int4*)(Bs_lo + row * 72 + c8) = *(const int4*)(Blo + soff);
            }
        } else {
            #pragma unroll
            for (int i = 0; i < 4; i++) {
                int g = tid + i * 256;
                int row = g >> 4, c8 = (g & 15) * 8;
                size_t soff = (size_t)(kc * 64 + row) * Nc + n0 + c8;
                *(int4*)(Bs_hi + row * 136 + c8) = *(const int4*)(Bhi + soff);
                *(int4*)(Bs_lo + row * 136 + c8) = *(const int4*)(Blo + soff);
            }
        }
        __syncthreads();

        #pragma unroll
        for (int ks = 0; ks < 4; ks++) {
            typename BFrag<BT>::T bh[2], bl[2];
            #pragma unroll
            for (int ni = 0; ni < 2; ni++) {
                BFrag<BT>::load(bh[ni], Bs_hi, n_off + 16 * ni, ks);
                BFrag<BT>::load(bl[ni], Bs_lo, n_off + 16 * ni, ks);
            }
            #pragma unroll
            for (int mi = 0; mi < 4; mi++) {
                wmma::fragment<wmma::matrix_a, 16, 16, 16, __nv_bfloat16, wmma::row_major> ah, al;
                wmma::load_matrix_sync(ah, As_hi + (m_off + 16 * mi) * 72 + ks * 16, 72);
                wmma::load_matrix_sync(al, As_lo + (m_off + 16 * mi) * 72 + ks * 16, 72);
                #pragma unroll
                for (int ni = 0; ni < 2; ni++) {
                    wmma::mma_sync(acc[mi][ni], ah, bh[ni], acc[mi][ni]);
                    wmma::mma_sync(acc[mi][ni], ah, bl[ni], acc[mi][ni]);
                    wmma::mma_sync(acc[mi][ni], al, bh[ni], acc[mi][ni]);
                }
            }
        }
    }

    __syncthreads();
    #pragma unroll
    for (int mi = 0; mi < 4; mi++)
        #pragma unroll
        for (int ni = 0; ni < 2; ni++)
            wmma::store_matrix_sync(Ds + (m_off + 16 * mi) * 132 + n_off + 16 * ni,
                                    acc[mi][ni], 132, wmma::mem_row_major);
    __syncthreads();

    const int r = tid >> 1, ch = (tid & 1) * 64;
    const float* drow = Ds + r * 132 + ch;
    if (SPLITOUT) {
        #pragma unroll
        for (int j4 = 0; j4 < 8; j4++) {
            float v[8];
            #pragma unroll
            for (int jj = 0; jj < 8; jj++) {
                float t = drow[j4 * 8 + jj];
                v[jj] = TANH_ ? tanhf(t) : t;
            }
            uint4 ho, lo;
            uint32_t* hp = (uint32_t*)&ho;
            uint32_t* lp = (uint32_t*)&lo;
            #pragma unroll
            for (int p = 0; p < 4; p++) {
                __nv_bfloat162 h = __floats2bfloat162_rn(v[2 * p], v[2 * p + 1]);
                float r0 = v[2 * p]     - __bfloat162float(h.x);
                float r1 = v[2 * p + 1] - __bfloat162float(h.y);
                __nv_bfloat162 l = __floats2bfloat162_rn(r0, r1);
                hp[p] = *(uint32_t*)&h;
                lp[p] = *(uint32_t*)&l;
            }
            size_t o = (size_t)(m0 + r) * ldc + coff + n0 + ch + j4 * 8;
            *(uint4*)(Chi + o) = ho;
            *(uint4*)(Clo + o) = lo;
        }
    } else {
        #pragma unroll
        for (int jv = 0; jv < 16; jv++) {
            float4 vv;
            float* vp = (float*)&vv;
            #pragma unroll
            for (int j = 0; j < 4; j++) {
                int col = n0 + ch + jv * 4 + j;
                float val = drow[jv * 4 + j];
                if (TANH_) val = tanhf(val);
                if (BIASRELU_) { val += bias[col]; val = fmaxf(val, 0.0f); }
                vp[j] = val;
            }
            *(float4*)(Cf + (size_t)(m0 + r) * ldc + coff + n0 + ch + jv * 4) = vv;
        }
    }
}

// ============================================================
// Tensor-core fused logit kernel, cp.async 2-stage pipeline
//   ws[m] = sum_h tanh( A[m,:] . W1[h,:] ) * y[m/16, h]
// Flattened (hc,kc) loop; stage t -> buffer t&1. Since KCH is even,
// every hc's last chunk is in buffer 1 -> Ds unions with buffer 1
// while the next hc's prefetch proceeds in buffer 0.
// ============================================================
// dyn smem:
//   stage s at s*73728: As_hi(18432) As_lo(18432) Bs_hi(18432) Bs_lo(18432)
//   ys at 147456: 8x512 fp32 (16384)      total 163840
//   Ds = stage1 region (128x132 fp32 = 67584 <= 73728)
#define WS4_SMEM 163840
#define STG 73728

template<int KD>
__global__ void __launch_bounds__(256, 1)
ws_mma(const __nv_bfloat16* __restrict__ Ahi, const __nv_bfloat16* __restrict__ Alo,
       const __nv_bfloat16* __restrict__ Whi, const __nv_bfloat16* __restrict__ Wlo,
       const float* __restrict__ y, float* __restrict__ ws)
{
    extern __shared__ char sm[];
    constexpr int KCH = KD / 64;
    constexpr int T = 4 * KCH;

    float* ys = (float*)(sm + 2 * STG);
    float* Ds = (float*)(sm + STG);         // unions with stage 1

    const int tid = threadIdx.x;
    const int wid = tid >> 5;
    const int m0 = blockIdx.x * 128;
    const int node0 = m0 >> 4;
    const int m_off = (wid & 1) * 64;
    const int n_off = (wid >> 1) * 32;
    const uint32_t smb = smem_u32(sm);

    // per-thread staging coordinates (16B granules)
    const int srow = tid >> 3;              // 0..31 (+32*i)
    const int sc8 = (tid & 7) * 8;          // element offset, 16B granule

    // issue cp.async loads for flattened chunk t into buffer t&1
    auto issue = [&](int t) {
        const int hc = t / KCH, kc = t % KCH;
        const uint32_t b = smb + (uint32_t)(t & 1) * STG;
        #pragma unroll
        for (int i = 0; i < 4; i++) {
            int row = srow + i * 32;
            uint32_t so = (uint32_t)(row * 72 + sc8) * 2;
            size_t ga = (size_t)(m0 + row) * KD + kc * 64 + sc8;
            CP16(b + so,         Ahi + ga);
            CP16(b + 18432 + so, Alo + ga);
            size_t gb = (size_t)(hc * 128 + row) * KD + kc * 64 + sc8;
            CP16(b + 36864 + so, Whi + gb);
            CP16(b + 55296 + so, Wlo + gb);
        }
        CP_COMMIT();
    };

    // stage ys (plain loads; overlap with first cp.async groups)
    {
        const float4* src = (const float4*)(y + (size_t)node0 * HH);
        #pragma unroll
        for (int i = 0; i < 4; i++)
            ((float4*)ys)[tid + i * 256] = src[tid + i * 256];
    }

    issue(0);

    float wsacc = 0.0f;
    wmma::fragment<wmma::accumulator, 16, 16, 16, float> acc[4][2];

    for (int t = 0; t < T; t++) {
        const int kc = t % KCH;
        if (kc == 0) {
            #pragma unroll
            for (int mi = 0; mi < 4; mi++)
                #pragma unroll
                for (int ni = 0; ni < 2; ni++)
                    wmma::fill_fragment(acc[mi][ni], 0.0f);
        }

        __syncthreads();                    // all warps done with buffer (t+1)&1
        if (t + 1 < T) { issue(t + 1); CP_WAIT1(); }
        else           { CP_WAIT0(); }
        __syncthreads();                    // chunk t visible to all

        __nv_bfloat16* buf   = (__nv_bfloat16*)(sm + (t & 1) * STG);
        __nv_bfloat16* As_hi = buf;
        __nv_bfloat16* As_lo = buf + 18432 / 2;
        __nv_bfloat16* Bs_hi = buf + 36864 / 2;
        __nv_bfloat16* Bs_lo = buf + 55296 / 2;

        #pragma unroll
        for (int ks = 0; ks < 4; ks++) {
            wmma::fragment<wmma::matrix_b, 16, 16, 16, __nv_bfloat16, wmma::col_major> bh[2], bl[2];
            #pragma unroll
            for (int ni = 0; ni < 2; ni++) {
                wmma::load_matrix_sync(bh[ni], Bs_hi + (n_off + 16 * ni) * 72 + ks * 16, 72);
                wmma::load_matrix_sync(bl[ni], Bs_lo + (n_off + 16 * ni) * 72 + ks * 16, 72);
            }
            #pragma unroll
            for (int mi = 0; mi < 4; mi++) {
                wmma::fragment<wmma::matrix_a, 16, 16, 16, __nv_bfloat16, wmma::row_major> ah, al;
                wmma::load_matrix_sync(ah, As_hi + (m_off + 16 * mi) * 72 + ks * 16, 72);
                wmma::load_matrix_sync(al, As_lo + (m_off + 16 * mi) * 72 + ks * 16, 72);
                #pragma unroll
                for (int ni = 0; ni < 2; ni++) {
                    wmma::mma_sync(acc[mi][ni], ah, bh[ni], acc[mi][ni]);
                    wmma::mma_sync(acc[mi][ni], ah, bl[ni], acc[mi][ni]);
                    wmma::mma_sync(acc[mi][ni], al, bh[ni], acc[mi][ni]);
                }
            }
        }

        if (kc == KCH - 1) {
            // KCH even -> this chunk sits in buffer 1; Ds (buffer-1 union) is
            // safe: prefetch for t+1 went into buffer 0.
            const int hc = t / KCH;
            __syncthreads();
            #pragma unroll
            for (int mi = 0; mi < 4; mi++)
                #pragma unroll
                for (int ni = 0; ni < 2; ni++)
                    wmma::store_matrix_sync(Ds + (m_off + 16 * mi) * 132 + n_off + 16 * ni,
                                            acc[mi][ni], 132, wmma::mem_row_major);
            __syncthreads();
            {
                int r = tid >> 1, ch = (tid & 1) * 64;
                const float* drow = Ds + r * 132 + ch;
                const float* yrow = ys + (r >> 4) * HH + hc * 128 + ch;
                float p = 0.0f;
                #pragma unroll
                for (int j = 0; j < 64; j++)
                    p = fmaf(tanhf(drow[j]), yrow[j], p);
                wsacc += p;
            }
            // top-of-loop __syncthreads covers Ds reads before the next
            // issue into buffer 1 (which happens one iteration later).
        }
    }

    float other = __shfl_xor_sync(0xffffffffu, wsacc, 1);
    if ((tid & 1) == 0)
        ws[m0 + (tid >> 1)] = wsacc + other;
}

// ============================================================
// Softmax (scaled / masked) + weighted aggregation (unchanged)
// ============================================================
__global__ void __launch_bounds__(128)
softmax_agg(const float* __restrict__ wsn, const float* __restrict__ wse,
            const int* __restrict__ mask, const float* __restrict__ neibs,
            const float* __restrict__ edges,
            float* __restrict__ aggn, float* __restrict__ agge)
{
    const int n = blockIdx.x;
    const int tid = threadIdx.x;
    __shared__ float s1[16], s2[16];
    if (tid < 16) {
        s1[tid] = wsn[n * 16 + tid] * 0.04419417382415922f;  // 1/sqrt(512)
        s2[tid] = wse[n * 16 + tid] - 9999999.0f * (float)mask[n * 16 + tid];
    }
    __syncthreads();

    float w1[16], w2[16];
    float m1 = -1e30f, m2 = -1e30f;
    #pragma unroll
    for (int k = 0; k < 16; k++) {
        m1 = fmaxf(m1, s1[k]);
        m2 = fmaxf(m2, s2[k]);
    }
    float t1 = 0.0f, t2 = 0.0f;
    #pragma unroll
    for (int k = 0; k < 16; k++) {
        w1[k] = expf(s1[k] - m1); t1 += w1[k];
        w2[k] = expf(s2[k] - m2); t2 += w2[k];
    }
    const float r1 = 1.0f / t1, r2 = 1.0f / t2;

    #pragma unroll
    for (int p = 0; p < 2; p++) {
        int d = tid + p * 128;
        float acc = 0.0f;
        #pragma unroll
        for (int k = 0; k < 16; k++)
            acc = fmaf(w1[k], neibs[((size_t)n * 16 + k) * DD + d], acc);
        aggn[(size_t)n * DD + d] = acc * r1;
    }
    {
        int d = tid;
        float acc = 0.0f;
        #pragma unroll
        for (int k = 0; k < 16; k++)
            acc = fmaf(w2[k], edges[((size_t)n * 16 + k) * EE + d], acc);
        agge[(size_t)n * EE + d] = acc * r2;
    }
}

// ============================================================
extern "C" void kernel_launch(void* const* d_in, const int* in_sizes, int n_in,
                              void* d_out, int out_size)
{
    const float* x     = (const float*)d_in[0];
    const float* neibs = (const float*)d_in[1];
    const float* edge  = (const float*)d_in[2];
    const int*   mask  = (const int*)  d_in[3];
    const float* W1x   = (const float*)d_in[4];
    const float* W2x   = (const float*)d_in[5];
    const float* W1n   = (const float*)d_in[6];
    const float* W2n   = (const float*)d_in[7];
    const float* W1e   = (const float*)d_in[8];
    const float* W2e   = (const float*)d_in[9];
    const float* Wfx   = (const float*)d_in[10];
    const float* bfx   = (const float*)d_in[11];
    const float* Wfn   = (const float*)d_in[12];
    const float* bfn   = (const float*)d_in[13];
    const float* Wfe   = (const float*)d_in[14];
    const float* bfe   = (const float*)d_in[15];
    float* out = (float*)d_out;

    float *yn, *ye, *wsn, *wse, *aggn, *agge;
    cudaGetSymbolAddress((void**)&yn,   g_yn);
    cudaGetSymbolAddress((void**)&ye,   g_ye);
    cudaGetSymbolAddress((void**)&wsn,  g_wsn);
    cudaGetSymbolAddress((void**)&wse,  g_wse);
    cudaGetSymbolAddress((void**)&aggn, g_aggn);
    cudaGetSymbolAddress((void**)&agge, g_agge);

    __nv_bfloat16 *nhi, *nlo, *ehi, *elo, *w1nhi, *w1nlo, *w1ehi, *w1elo;
    __nv_bfloat16 *xhi, *xlo, *h1hi, *h1lo, *xahi, *xalo, *anhi, *anlo, *aehi, *aelo;
    __nv_bfloat16 *w1xhi, *w1xlo, *w2xhi, *w2xlo, *w2nhi, *w2nlo, *w2ehi, *w2elo;
    __nv_bfloat16 *wfxhi, *wfxlo, *wfnhi, *wfnlo, *wfehi, *wfelo;
    cudaGetSymbolAddress((void**)&nhi,   g_nhi);
    cudaGetSymbolAddress((void**)&nlo,   g_nlo);
    cudaGetSymbolAddress((void**)&ehi,   g_ehi);
    cudaGetSymbolAddress((void**)&elo,   g_elo);
    cudaGetSymbolAddress((void**)&w1nhi, g_w1nhi);
    cudaGetSymbolAddress((void**)&w1nlo, g_w1nlo);
    cudaGetSymbolAddress((void**)&w1ehi, g_w1ehi);
    cudaGetSymbolAddress((void**)&w1elo, g_w1elo);
    cudaGetSymbolAddress((void**)&xhi,   g_xhi);
    cudaGetSymbolAddress((void**)&xlo,   g_xlo);
    cudaGetSymbolAddress((void**)&h1hi,  g_h1hi);
    cudaGetSymbolAddress((void**)&h1lo,  g_h1lo);
    cudaGetSymbolAddress((void**)&xahi,  g_xahi);
    cudaGetSymbolAddress((void**)&xalo,  g_xalo);
    cudaGetSymbolAddress((void**)&anhi,  g_anhi);
    cudaGetSymbolAddress((void**)&anlo,  g_anlo);
    cudaGetSymbolAddress((void**)&aehi,  g_aehi);
    cudaGetSymbolAddress((void**)&aelo,  g_aelo);
    cudaGetSymbolAddress((void**)&w1xhi, g_w1xhi);
    cudaGetSymbolAddress((void**)&w1xlo, g_w1xlo);
    cudaGetSymbolAddress((void**)&w2xhi, g_w2xhi);
    cudaGetSymbolAddress((void**)&w2xlo, g_w2xlo);
    cudaGetSymbolAddress((void**)&w2nhi, g_w2nhi);
    cudaGetSymbolAddress((void**)&w2nlo, g_w2nlo);
    cudaGetSymbolAddress((void**)&w2ehi, g_w2ehi);
    cudaGetSymbolAddress((void**)&w2elo, g_w2elo);
    cudaGetSymbolAddress((void**)&wfxhi, g_wfxhi);
    cudaGetSymbolAddress((void**)&wfxlo, g_wfxlo);
    cudaGetSymbolAddress((void**)&wfnhi, g_wfnhi);
    cudaGetSymbolAddress((void**)&wfnlo, g_wfnlo);
    cudaGetSymbolAddress((void**)&wfehi, g_wfehi);
    cudaGetSymbolAddress((void**)&wfelo, g_wfelo);

    cudaFuncSetAttribute(ws_mma<DD>, cudaFuncAttributeMaxDynamicSharedMemorySize, WS4_SMEM);
    cudaFuncSetAttribute(ws_mma<EE>, cudaFuncAttributeMaxDynamicSharedMemorySize, WS4_SMEM);
    cudaFuncSetAttribute(wgemm2<true,  true,  false, true >, cudaFuncAttributeMaxDynamicSharedMemorySize, WG2_SMEM);
    cudaFuncSetAttribute(wgemm2<true,  false, false, true >, cudaFuncAttributeMaxDynamicSharedMemorySize, WG2_SMEM);
    cudaFuncSetAttribute(wgemm2<false, false, false, false>, cudaFuncAttributeMaxDynamicSharedMemorySize, WG2_SMEM);
    cudaFuncSetAttribute(wgemm2<true,  false, true,  false>, cudaFuncAttributeMaxDynamicSharedMemorySize, WG2_SMEM);

    dim3 blk(256);

    // ---- splits ----
    split_kernel<<<(NN*DD/4 + 255)/256, blk>>>(x,   xhi,   xlo,   NN*DD/4);
    split_kernel<<<(HH*DD/4 + 255)/256, blk>>>(W1x, w1xhi, w1xlo, HH*DD/4);
    split_kernel<<<(HH*HH/4 + 255)/256, blk>>>(W2x, w2xhi, w2xlo, HH*HH/4);
    split_kernel<<<(HH*HH/4 + 255)/256, blk>>>(W2n, w2nhi, w2nlo, HH*HH/4);
    split_kernel<<<(HH*HH/4 + 255)/256, blk>>>(W2e, w2ehi, w2elo, HH*HH/4);
    split_kernel<<<(NN*KNB*DD/4 + 255)/256, blk>>>(neibs, nhi, nlo, NN*KNB*DD/4);
    split_kernel<<<(NN*KNB*EE/4 + 255)/256, blk>>>(edge,  ehi, elo, NN*KNB*EE/4);
    split_kernel<<<(HH*DD/4 + 255)/256, blk>>>(W1n, w1nhi, w1nlo, HH*DD/4);
    split_kernel<<<(HH*EE/4 + 255)/256, blk>>>(W1e, w1ehi, w1elo, HH*EE/4);
    split_kernel<<<(OO*DD/4 + 255)/256, blk>>>(Wfx, wfxhi, wfxlo, OO*DD/4);
    split_kernel<<<(OO*DD/4 + 255)/256, blk>>>(Wfn, wfnhi, wfnlo, OO*DD/4);
    split_kernel<<<(OO*EE/4 + 255)/256, blk>>>(Wfe, wfehi, wfelo, OO*EE/4);

    // ---- x_att chain on tensor cores ----
    wgemm2<true, true, false, true><<<dim3(HH/128, NN/128), blk, WG2_SMEM>>>(
        xhi, xlo, w1xhi, w1xlo, nullptr, nullptr, h1hi, h1lo, HH, DD, HH, 0);
    wgemm2<true, false, false, true><<<dim3(HH/128, NN/128), blk, WG2_SMEM>>>(
        h1hi, h1lo, w2xhi, w2xlo, nullptr, nullptr, xahi, xalo, HH, HH, HH, 0);
    wgemm2<false, false, false, false><<<dim3(HH/128, NN/128), blk, WG2_SMEM>>>(
        xahi, xalo, w2nhi, w2nlo, nullptr, yn, nullptr, nullptr, HH, HH, HH, 0);
    wgemm2<false, false, false, false><<<dim3(HH/128, NN/128), blk, WG2_SMEM>>>(
        xahi, xalo, w2ehi, w2elo, nullptr, ye, nullptr, nullptr, HH, HH, HH, 0);

    // ---- attention logits (cp.async pipelined tensor cores) ----
    ws_mma<DD><<<(NN * KNB) / 128, blk, WS4_SMEM>>>(nhi, nlo, w1nhi, w1nlo, yn, wsn);
    ws_mma<EE><<<(NN * KNB) / 128, blk, WS4_SMEM>>>(ehi, elo, w1ehi, w1elo, ye, wse);

    // ---- softmax + aggregation ----
    softmax_agg<<<NN, 128>>>(wsn, wse, mask, neibs, edge, aggn, agge);

    // ---- output GEMMs on tensor cores ----
    split_kernel<<<(NN*DD/4 + 255)/256, blk>>>(aggn, anhi, anlo, NN*DD/4);
    split_kernel<<<(NN*EE/4 + 255)/256, blk>>>(agge, aehi, aelo, NN*EE/4);

    wgemm2<true, false, true, false><<<dim3(OO/128, NN/128), blk, WG2_SMEM>>>(
        xhi, xlo, wfxhi, wfxlo, bfx, out, nullptr, nullptr, OO, DD, 3*OO, 0);
    wgemm2<true, false, true, false><<<dim3(OO/128, NN/128), blk, WG2_SMEM>>>(
        anhi, anlo, wfnhi, wfnlo, bfn, out, nullptr, nullptr, OO, DD, 3*OO, OO);
    wgemm2<true, false, true, false><<<dim3(OO/128, NN/128), blk, WG2_SMEM>>>(
        aehi, aelo, wfehi, wfelo, bfe, out, nullptr, nullptr, OO, EE, 3*OO, 2*OO);
}

// round 14
// speedup vs baseline: 1.0876x; 1.0876x over previous
#include <cuda_runtime.h>
#include <cuda_bf16.h>
#include <mma.h>
#include <math.h>
#include <stdint.h>

using namespace nvcuda;

#define NN 8192
#define KNB 16
#define DD 256
#define EE 128
#define HH 512
#define OO 256

// ---- scratch (no allocations allowed; __device__ globals) ----
__device__ float g_yn[NN * HH];
__device__ float g_ye[NN * HH];
__device__ float g_wsn[NN * KNB];
__device__ float g_wse[NN * KNB];
__device__ float g_aggn[NN * DD];
__device__ float g_agge[NN * EE];
// bf16 hi/lo splits: ws inputs
__device__ __nv_bfloat16 g_nhi[NN * KNB * DD];
__device__ __nv_bfloat16 g_nlo[NN * KNB * DD];
__device__ __nv_bfloat16 g_ehi[NN * KNB * EE];
__device__ __nv_bfloat16 g_elo[NN * KNB * EE];
__device__ __nv_bfloat16 g_w1nhi[HH * DD];
__device__ __nv_bfloat16 g_w1nlo[HH * DD];
__device__ __nv_bfloat16 g_w1ehi[HH * EE];
__device__ __nv_bfloat16 g_w1elo[HH * EE];
// chain inputs/activations (hi/lo)
__device__ __nv_bfloat16 g_xhi[NN * DD];
__device__ __nv_bfloat16 g_xlo[NN * DD];
__device__ __nv_bfloat16 g_h1hi[NN * HH];
__device__ __nv_bfloat16 g_h1lo[NN * HH];
__device__ __nv_bfloat16 g_xahi[NN * HH];
__device__ __nv_bfloat16 g_xalo[NN * HH];
__device__ __nv_bfloat16 g_anhi[NN * DD];
__device__ __nv_bfloat16 g_anlo[NN * DD];
__device__ __nv_bfloat16 g_aehi[NN * EE];
__device__ __nv_bfloat16 g_aelo[NN * EE];
// weight splits
__device__ __nv_bfloat16 g_w1xhi[HH * DD];
__device__ __nv_bfloat16 g_w1xlo[HH * DD];
__device__ __nv_bfloat16 g_w2xhi[HH * HH];
__device__ __nv_bfloat16 g_w2xlo[HH * HH];
__device__ __nv_bfloat16 g_w2nhi[HH * HH];
__device__ __nv_bfloat16 g_w2nlo[HH * HH];
__device__ __nv_bfloat16 g_w2ehi[HH * HH];
__device__ __nv_bfloat16 g_w2elo[HH * HH];
__device__ __nv_bfloat16 g_wfxhi[OO * DD];
__device__ __nv_bfloat16 g_wfxlo[OO * DD];
__device__ __nv_bfloat16 g_wfnhi[OO * DD];
__device__ __nv_bfloat16 g_wfnlo[OO * DD];
__device__ __nv_bfloat16 g_wfehi[OO * EE];
__device__ __nv_bfloat16 g_wfelo[OO * EE];

// ============================================================
// cp.async helpers
// ============================================================
__device__ __forceinline__ uint32_t smem_u32(const void* p) {
    uint32_t r;
    asm("{ .reg .u64 t; cvta.to.shared.u64 t, %1; cvt.u32.u64 %0, t; }"
        : "=r"(r) : "l"(p));
    return r;
}
#define CP16(dst_u32, src_ptr) \
    asm volatile("cp.async.cg.shared.global [%0], [%1], 16;" \
                 :: "r"(dst_u32), "l"(src_ptr) : "memory")
#define CP_COMMIT() asm volatile("cp.async.commit_group;" ::: "memory")
#define CP_WAIT1()  asm volatile("cp.async.wait_group 1;" ::: "memory")
#define CP_WAIT0()  asm volatile("cp.async.wait_group 0;" ::: "memory")

// ============================================================
// fp32 -> bf16 hi/lo split (elementwise, float4-vectorized)
// ============================================================
__global__ void __launch_bounds__(256)
split_kernel(const float* __restrict__ src, __nv_bfloat16* __restrict__ hi,
             __nv_bfloat16* __restrict__ lo, int n4)
{
    int i = blockIdx.x * blockDim.x + threadIdx.x;
    if (i >= n4) return;
    float4 v = ((const float4*)src)[i];
    __nv_bfloat162 h01 = __floats2bfloat162_rn(v.x, v.y);
    __nv_bfloat162 h23 = __floats2bfloat162_rn(v.z, v.w);
    float rx = v.x - __bfloat162float(h01.x);
    float ry = v.y - __bfloat162float(h01.y);
    float rz = v.z - __bfloat162float(h23.x);
    float rw = v.w - __bfloat162float(h23.y);
    __nv_bfloat162 l01 = __floats2bfloat162_rn(rx, ry);
    __nv_bfloat162 l23 = __floats2bfloat162_rn(rz, rw);
    uint2 ho, loo;
    ho.x  = *(uint32_t*)&h01; ho.y  = *(uint32_t*)&h23;
    loo.x = *(uint32_t*)&l01; loo.y = *(uint32_t*)&l23;
    ((uint2*)hi)[i] = ho;
    ((uint2*)lo)[i] = loo;
}

// ============================================================
// B-fragment handling for wgemm2 (unchanged from R11)
// ============================================================
template<bool BT> struct BFrag;
template<> struct BFrag<true> {
    using T = wmma::fragment<wmma::matrix_b, 16, 16, 16, __nv_bfloat16, wmma::col_major>;
    static __device__ __forceinline__ void load(T& f, const __nv_bfloat16* base,
                                                int n_idx, int ks) {
        wmma::load_matrix_sync(f, base + n_idx * 72 + ks * 16, 72);
    }
};
template<> struct BFrag<false> {
    using T = wmma::fragment<wmma::matrix_b, 16, 16, 16, __nv_bfloat16, wmma::row_major>;
    static __device__ __forceinline__ void load(T& f, const __nv_bfloat16* base,
                                                int n_idx, int ks) {
        wmma::load_matrix_sync(f, base + (ks * 16) * 136 + n_idx, 136);
    }
};

// ============================================================
// Generic WMMA GEMM (UNCHANGED from passing R11)
// ============================================================
#define WG2_SMEM 73728

template<bool BT, bool TANH_, bool BIASRELU_, bool SPLITOUT>
__global__ void __launch_bounds__(256, 2)
wgemm2(const __nv_bfloat16* __restrict__ Ahi, const __nv_bfloat16* __restrict__ Alo,
       const __nv_bfloat16* __restrict__ Bhi, const __nv_bfloat16* __restrict__ Blo,
       const float* __restrict__ bias,
       float* __restrict__ Cf, __nv_bfloat16* __restrict__ Chi, __nv_bfloat16* __restrict__ Clo,
       int Nc, int Kc, int ldc, int coff)
{
    extern __shared__ char sm[];
    __nv_bfloat16* As_hi = (__nv_bfloat16*)(sm);
    __nv_bfloat16* As_lo = (__nv_bfloat16*)(sm + 18432);
    __nv_bfloat16* Bs_hi = (__nv_bfloat16*)(sm + 36864);
    __nv_bfloat16* Bs_lo = (__nv_bfloat16*)(sm + 55296);
    float* Ds = (float*)sm;

    const int tid = threadIdx.x;
    const int wid = tid >> 5;
    const int m0 = blockIdx.y * 128;
    const int n0 = blockIdx.x * 128;
    const int m_off = (wid & 1) * 64;
    const int n_off = (wid >> 1) * 32;

    wmma::fragment<wmma::accumulator, 16, 16, 16, float> acc[4][2];
    #pragma unroll
    for (int mi = 0; mi < 4; mi++)
        #pragma unroll
        for (int ni = 0; ni < 2; ni++)
            wmma::fill_fragment(acc[mi][ni], 0.0f);

    const int KCH = Kc >> 6;
    for (int kc = 0; kc < KCH; kc++) {
        __syncthreads();
        #pragma unroll
        for (int i = 0; i < 4; i++) {
            int g = tid + i * 256;
            int row = g >> 3, c8 = (g & 7) * 8;
            size_t soff = (size_t)(m0 + row) * Kc + kc * 64 + c8;
            *(int4*)(As_hi + row * 72 + c8) = *(const int4*)(Ahi + soff);
            *(int4*)(As_lo + row * 72 + c8) = *(const int4*)(Alo + soff);
        }
        if (BT) {
            #pragma unroll
            for (int i = 0; i < 4; i++) {
                int g = tid + i * 256;
                int row = g >> 3, c8 = (g & 7) * 8;
                size_t soff = (size_t)(n0 + row) * Kc + kc * 64 + c8;
                *(int4*)(Bs_hi + row * 72 + c8) = *(const int4*)(Bhi + soff);
                *(int4*)(Bs_lo + row * 72 + c8) = *(const int4*)(Blo + soff);
            }
        } else {
            #pragma unroll
            for (int i = 0; i < 4; i++) {
                int g = tid + i * 256;
                int row = g >> 4, c8 = (g & 15) * 8;
                size_t soff = (size_t)(kc * 64 + row) * Nc + n0 + c8;
                *(int4*)(Bs_hi + row * 136 + c8) = *(const int4*)(Bhi + soff);
                *(int4*)(Bs_lo + row * 136 + c8) = *(const int4*)(Blo + soff);
            }
        }
        __syncthreads();

        #pragma unroll
        for (int ks = 0; ks < 4; ks++) {
            typename BFrag<BT>::T bh[2], bl[2];
            #pragma unroll
            for (int ni = 0; ni < 2; ni++) {
                BFrag<BT>::load(bh[ni], Bs_hi, n_off + 16 * ni, ks);
                BFrag<BT>::load(bl[ni], Bs_lo, n_off + 16 * ni, ks);
            }
            #pragma unroll
            for (int mi = 0; mi < 4; mi++) {
                wmma::fragment<wmma::matrix_a, 16, 16, 16, __nv_bfloat16, wmma::row_major> ah, al;
                wmma::load_matrix_sync(ah, As_hi + (m_off + 16 * mi) * 72 + ks * 16, 72);
                wmma::load_matrix_sync(al, As_lo + (m_off + 16 * mi) * 72 + ks * 16, 72);
                #pragma unroll
                for (int ni = 0; ni < 2; ni++) {
                    wmma::mma_sync(acc[mi][ni], ah, bh[ni], acc[mi][ni]);
                    wmma::mma_sync(acc[mi][ni], ah, bl[ni], acc[mi][ni]);
                    wmma::mma_sync(acc[mi][ni], al, bh[ni], acc[mi][ni]);
                }
            }
        }
    }

    __syncthreads();
    #pragma unroll
    for (int mi = 0; mi < 4; mi++)
        #pragma unroll
        for (int ni = 0; ni < 2; ni++)
            wmma::store_matrix_sync(Ds + (m_off + 16 * mi) * 132 + n_off + 16 * ni,
                                    acc[mi][ni], 132, wmma::mem_row_major);
    __syncthreads();

    const int r = tid >> 1, ch = (tid & 1) * 64;
    const float* drow = Ds + r * 132 + ch;
    if (SPLITOUT) {
        #pragma unroll
        for (int j4 = 0; j4 < 8; j4++) {
            float v[8];
            #pragma unroll
            for (int jj = 0; jj < 8; jj++) {
                float t = drow[j4 * 8 + jj];
                v[jj] = TANH_ ? tanhf(t) : t;
            }
            uint4 ho, lo;
            uint32_t* hp = (uint32_t*)&ho;
            uint32_t* lp = (uint32_t*)&lo;
            #pragma unroll
            for (int p = 0; p < 4; p++) {
                __nv_bfloat162 h = __floats2bfloat162_rn(v[2 * p], v[2 * p + 1]);
                float r0 = v[2 * p]     - __bfloat162float(h.x);
                float r1 = v[2 * p + 1] - __bfloat162float(h.y);
                __nv_bfloat162 l = __floats2bfloat162_rn(r0, r1);
                hp[p] = *(uint32_t*)&h;
                lp[p] = *(uint32_t*)&l;
            }
            size_t o = (size_t)(m0 + r) * ldc + coff + n0 + ch + j4 * 8;
            *(uint4*)(Chi + o) = ho;
            *(uint4*)(Clo + o) = lo;
        }
    } else {
        #pragma unroll
        for (int jv = 0; jv < 16; jv++) {
            float4 vv;
            float* vp = (float*)&vv;
            #pragma unroll
            for (int j = 0; j < 4; j++) {
                int col = n0 + ch + jv * 4 + j;
                float val = drow[jv * 4 + j];
                if (TANH_) val = tanhf(val);
                if (BIASRELU_) { val += bias[col]; val = fmaxf(val, 0.0f); }
                vp[j] = val;
            }
            *(float4*)(Cf + (size_t)(m0 + r) * ldc + coff + n0 + ch + jv * 4) = vv;
        }
    }
}

// ============================================================
// Tensor-core fused logit kernel: cp.async 2-stage pipeline with
// SMALL (32-wide K) stages so 2 CTAs/SM are retained.
//   ws[m] = sum_h tanh( A[m,:] . W1[h,:] ) * y[m/16, h]
// Per-hc pipeline (drained at hc boundary so Ds can union the stages).
// ============================================================
// dyn smem:
//   stage s at s*40960: As_hi 128x40 (10240) | As_lo | Bs_hi | Bs_lo
//   ys at 81920: 8x512 fp32 (16384)        total 98304  -> 2 CTAs/SM
//   Ds (128x132 fp32 = 67584) unions stages, used only when drained
#define WS5_SMEM 98304
#define STG5 40960

template<int KD>
__global__ void __launch_bounds__(256, 2)
ws_mma(const __nv_bfloat16* __restrict__ Ahi, const __nv_bfloat16* __restrict__ Alo,
       const __nv_bfloat16* __restrict__ Whi, const __nv_bfloat16* __restrict__ Wlo,
       const float* __restrict__ y, float* __restrict__ ws)
{
    extern __shared__ char sm[];
    constexpr int KCH = KD / 32;            // 32-wide chunks: 8 (DD) / 4 (EE)

    float* ys = (float*)(sm + 2 * STG5);
    float* Ds = (float*)sm;                 // unions stages (used when drained)

    const int tid = threadIdx.x;
    const int wid = tid >> 5;
    const int m0 = blockIdx.x * 128;
    const int node0 = m0 >> 4;
    const int m_off = (wid & 1) * 64;
    const int n_off = (wid >> 1) * 32;
    const uint32_t smb = smem_u32(sm);

    // per-thread staging coords: 512 granules(16B)/tensor/chunk -> 2/thread
    const int srow = tid >> 2;              // 0..63 (+64*i)
    const int sc8 = (tid & 3) * 8;          // col offset (8 elements = 16B)

    auto issue = [&](int hc, int kc) {
        const uint32_t b = smb + (uint32_t)(kc & 1) * STG5;
        #pragma unroll
        for (int i = 0; i < 2; i++) {
            int row = srow + i * 64;
            uint32_t so = (uint32_t)(row * 40 + sc8) * 2;
            size_t ga = (size_t)(m0 + row) * KD + kc * 32 + sc8;
            CP16(b + so,         Ahi + ga);
            CP16(b + 10240 + so, Alo + ga);
            size_t gb = (size_t)(hc * 128 + row) * KD + kc * 32 + sc8;
            CP16(b + 20480 + so, Whi + gb);
            CP16(b + 30720 + so, Wlo + gb);
        }
        CP_COMMIT();
    };

    // stage ys
    {
        const float4* src = (const float4*)(y + (size_t)node0 * HH);
        #pragma unroll
        for (int i = 0; i < 4; i++)
            ((float4*)ys)[tid + i * 256] = src[tid + i * 256];
    }

    float wsacc = 0.0f;

    for (int hc = 0; hc < 4; hc++) {
        wmma::fragment<wmma::accumulator, 16, 16, 16, float> acc[4][2];
        #pragma unroll
        for (int mi = 0; mi < 4; mi++)
            #pragma unroll
            for (int ni = 0; ni < 2; ni++)
                wmma::fill_fragment(acc[mi][ni], 0.0f);

        __syncthreads();        // Ds/stage reads of previous hc complete
        issue(hc, 0);

        for (int kc = 0; kc < KCH; kc++) {
            if (kc + 1 < KCH) { issue(hc, kc + 1); CP_WAIT1(); }
            else              { CP_WAIT0(); }
            __syncthreads();    // chunk kc visible

            __nv_bfloat16* buf   = (__nv_bfloat16*)(sm + (kc & 1) * STG5);
            __nv_bfloat16* As_hi = buf;
            __nv_bfloat16* As_lo = buf + 10240 / 2;
            __nv_bfloat16* Bs_hi = buf + 20480 / 2;
            __nv_bfloat16* Bs_lo = buf + 30720 / 2;

            #pragma unroll
            for (int ks = 0; ks < 2; ks++) {
                wmma::fragment<wmma::matrix_b, 16, 16, 16, __nv_bfloat16, wmma::col_major> bh[2], bl[2];
                #pragma unroll
                for (int ni = 0; ni < 2; ni++) {
                    wmma::load_matrix_sync(bh[ni], Bs_hi + (n_off + 16 * ni) * 40 + ks * 16, 40);
                    wmma::load_matrix_sync(bl[ni], Bs_lo + (n_off + 16 * ni) * 40 + ks * 16, 40);
                }
                #pragma unroll
                for (int mi = 0; mi < 4; mi++) {
                    wmma::fragment<wmma::matrix_a, 16, 16, 16, __nv_bfloat16, wmma::row_major> ah, al;
                    wmma::load_matrix_sync(ah, As_hi + (m_off + 16 * mi) * 40 + ks * 16, 40);
                    wmma::load_matrix_sync(al, As_lo + (m_off + 16 * mi) * 40 + ks * 16, 40);
                    #pragma unroll
                    for (int ni = 0; ni < 2; ni++) {
                        wmma::mma_sync(acc[mi][ni], ah, bh[ni], acc[mi][ni]);
                        wmma::mma_sync(acc[mi][ni], ah, bl[ni], acc[mi][ni]);
                        wmma::mma_sync(acc[mi][ni], al, bh[ni], acc[mi][ni]);
                    }
                }
            }
            __syncthreads();    // all warps done with buffer kc&1 before reuse
        }

        // pipeline drained (WAIT0 + syncs) -> Ds may union the stages
        #pragma unroll
        for (int mi = 0; mi < 4; mi++)
            #pragma unroll
            for (int ni = 0; ni < 2; ni++)
                wmma::store_matrix_sync(Ds + (m_off + 16 * mi) * 132 + n_off + 16 * ni,
                                        acc[mi][ni], 132, wmma::mem_row_major);
        __syncthreads();
        {
            int r = tid >> 1, ch = (tid & 1) * 64;
            const float* drow = Ds + r * 132 + ch;
            const float* yrow = ys + (r >> 4) * HH + hc * 128 + ch;
            float p = 0.0f;
            #pragma unroll
            for (int j = 0; j < 64; j++)
                p = fmaf(tanhf(drow[j]), yrow[j], p);
            wsacc += p;
        }
        // top-of-hc __syncthreads protects Ds before the next issue
    }

    float other = __shfl_xor_sync(0xffffffffu, wsacc, 1);
    if ((tid & 1) == 0)
        ws[m0 + (tid >> 1)] = wsacc + other;
}

// ============================================================
// Softmax (scaled / masked) + weighted aggregation (unchanged)
// ============================================================
__global__ void __launch_bounds__(128)
softmax_agg(const float* __restrict__ wsn, const float* __restrict__ wse,
            const int* __restrict__ mask, const float* __restrict__ neibs,
            const float* __restrict__ edges,
            float* __restrict__ aggn, float* __restrict__ agge)
{
    const int n = blockIdx.x;
    const int tid = threadIdx.x;
    __shared__ float s1[16], s2[16];
    if (tid < 16) {
        s1[tid] = wsn[n * 16 + tid] * 0.04419417382415922f;  // 1/sqrt(512)
        s2[tid] = wse[n * 16 + tid] - 9999999.0f * (float)mask[n * 16 + tid];
    }
    __syncthreads();

    float w1[16], w2[16];
    float m1 = -1e30f, m2 = -1e30f;
    #pragma unroll
    for (int k = 0; k < 16; k++) {
        m1 = fmaxf(m1, s1[k]);
        m2 = fmaxf(m2, s2[k]);
    }
    float t1 = 0.0f, t2 = 0.0f;
    #pragma unroll
    for (int k = 0; k < 16; k++) {
        w1[k] = expf(s1[k] - m1); t1 += w1[k];
        w2[k] = expf(s2[k] - m2); t2 += w2[k];
    }
    const float r1 = 1.0f / t1, r2 = 1.0f / t2;

    #pragma unroll
    for (int p = 0; p < 2; p++) {
        int d = tid + p * 128;
        float acc = 0.0f;
        #pragma unroll
        for (int k = 0; k < 16; k++)
            acc = fmaf(w1[k], neibs[((size_t)n * 16 + k) * DD + d], acc);
        aggn[(size_t)n * DD + d] = acc * r1;
    }
    {
        int d = tid;
        float acc = 0.0f;
        #pragma unroll
        for (int k = 0; k < 16; k++)
            acc = fmaf(w2[k], edges[((size_t)n * 16 + k) * EE + d], acc);
        agge[(size_t)n * EE + d] = acc * r2;
    }
}

// ============================================================
extern "C" void kernel_launch(void* const* d_in, const int* in_sizes, int n_in,
                              void* d_out, int out_size)
{
    const float* x     = (const float*)d_in[0];
    const float* neibs = (const float*)d_in[1];
    const float* edge  = (const float*)d_in[2];
    const int*   mask  = (const int*)  d_in[3];
    const float* W1x   = (const float*)d_in[4];
    const float* W2x   = (const float*)d_in[5];
    const float* W1n   = (const float*)d_in[6];
    const float* W2n   = (const float*)d_in[7];
    const float* W1e   = (const float*)d_in[8];
    const float* W2e   = (const float*)d_in[9];
    const float* Wfx   = (const float*)d_in[10];
    const float* bfx   = (const float*)d_in[11];
    const float* Wfn   = (const float*)d_in[12];
    const float* bfn   = (const float*)d_in[13];
    const float* Wfe   = (const float*)d_in[14];
    const float* bfe   = (const float*)d_in[15];
    float* out = (float*)d_out;

    float *yn, *ye, *wsn, *wse, *aggn, *agge;
    cudaGetSymbolAddress((void**)&yn,   g_yn);
    cudaGetSymbolAddress((void**)&ye,   g_ye);
    cudaGetSymbolAddress((void**)&wsn,  g_wsn);
    cudaGetSymbolAddress((void**)&wse,  g_wse);
    cudaGetSymbolAddress((void**)&aggn, g_aggn);
    cudaGetSymbolAddress((void**)&agge, g_agge);

    __nv_bfloat16 *nhi, *nlo, *ehi, *elo, *w1nhi, *w1nlo, *w1ehi, *w1elo;
    __nv_bfloat16 *xhi, *xlo, *h1hi, *h1lo, *xahi, *xalo, *anhi, *anlo, *aehi, *aelo;
    __nv_bfloat16 *w1xhi, *w1xlo, *w2xhi, *w2xlo, *w2nhi, *w2nlo, *w2ehi, *w2elo;
    __nv_bfloat16 *wfxhi, *wfxlo, *wfnhi, *wfnlo, *wfehi, *wfelo;
    cudaGetSymbolAddress((void**)&nhi,   g_nhi);
    cudaGetSymbolAddress((void**)&nlo,   g_nlo);
    cudaGetSymbolAddress((void**)&ehi,   g_ehi);
    cudaGetSymbolAddress((void**)&elo,   g_elo);
    cudaGetSymbolAddress((void**)&w1nhi, g_w1nhi);
    cudaGetSymbolAddress((void**)&w1nlo, g_w1nlo);
    cudaGetSymbolAddress((void**)&w1ehi, g_w1ehi);
    cudaGetSymbolAddress((void**)&w1elo, g_w1elo);
    cudaGetSymbolAddress((void**)&xhi,   g_xhi);
    cudaGetSymbolAddress((void**)&xlo,   g_xlo);
    cudaGetSymbolAddress((void**)&h1hi,  g_h1hi);
    cudaGetSymbolAddress((void**)&h1lo,  g_h1lo);
    cudaGetSymbolAddress((void**)&xahi,  g_xahi);
    cudaGetSymbolAddress((void**)&xalo,  g_xalo);
    cudaGetSymbolAddress((void**)&anhi,  g_anhi);
    cudaGetSymbolAddress((void**)&anlo,  g_anlo);
    cudaGetSymbolAddress((void**)&aehi,  g_aehi);
    cudaGetSymbolAddress((void**)&aelo,  g_aelo);
    cudaGetSymbolAddress((void**)&w1xhi, g_w1xhi);
    cudaGetSymbolAddress((void**)&w1xlo, g_w1xlo);
    cudaGetSymbolAddress((void**)&w2xhi, g_w2xhi);
    cudaGetSymbolAddress((void**)&w2xlo, g_w2xlo);
    cudaGetSymbolAddress((void**)&w2nhi, g_w2nhi);
    cudaGetSymbolAddress((void**)&w2nlo, g_w2nlo);
    cudaGetSymbolAddress((void**)&w2ehi, g_w2ehi);
    cudaGetSymbolAddress((void**)&w2elo, g_w2elo);
    cudaGetSymbolAddress((void**)&wfxhi, g_wfxhi);
    cudaGetSymbolAddress((void**)&wfxlo, g_wfxlo);
    cudaGetSymbolAddress((void**)&wfnhi, g_wfnhi);
    cudaGetSymbolAddress((void**)&wfnlo, g_wfnlo);
    cudaGetSymbolAddress((void**)&wfehi, g_wfehi);
    cudaGetSymbolAddress((void**)&wfelo, g_wfelo);

    cudaFuncSetAttribute(ws_mma<DD>, cudaFuncAttributeMaxDynamicSharedMemorySize, WS5_SMEM);
    cudaFuncSetAttribute(ws_mma<EE>, cudaFuncAttributeMaxDynamicSharedMemorySize, WS5_SMEM);
    cudaFuncSetAttribute(wgemm2<true,  true,  false, true >, cudaFuncAttributeMaxDynamicSharedMemorySize, WG2_SMEM);
    cudaFuncSetAttribute(wgemm2<true,  false, false, true >, cudaFuncAttributeMaxDynamicSharedMemorySize, WG2_SMEM);
    cudaFuncSetAttribute(wgemm2<false, false, false, false>, cudaFuncAttributeMaxDynamicSharedMemorySize, WG2_SMEM);
    cudaFuncSetAttribute(wgemm2<true,  false, true,  false>, cudaFuncAttributeMaxDynamicSharedMemorySize, WG2_SMEM);

    dim3 blk(256);

    // ---- splits ----
    split_kernel<<<(NN*DD/4 + 255)/256, blk>>>(x,   xhi,   xlo,   NN*DD/4);
    split_kernel<<<(HH*DD/4 + 255)/256, blk>>>(W1x, w1xhi, w1xlo, HH*DD/4);
    split_kernel<<<(HH*HH/4 + 255)/256, blk>>>(W2x, w2xhi, w2xlo, HH*HH/4);
    split_kernel<<<(HH*HH/4 + 255)/256, blk>>>(W2n, w2nhi, w2nlo, HH*HH/4);
    split_kernel<<<(HH*HH/4 + 255)/256, blk>>>(W2e, w2ehi, w2elo, HH*HH/4);
    split_kernel<<<(NN*KNB*DD/4 + 255)/256, blk>>>(neibs, nhi, nlo, NN*KNB*DD/4);
    split_kernel<<<(NN*KNB*EE/4 + 255)/256, blk>>>(edge,  ehi, elo, NN*KNB*EE/4);
    split_kernel<<<(HH*DD/4 + 255)/256, blk>>>(W1n, w1nhi, w1nlo, HH*DD/4);
    split_kernel<<<(HH*EE/4 + 255)/256, blk>>>(W1e, w1ehi, w1elo, HH*EE/4);
    split_kernel<<<(OO*DD/4 + 255)/256, blk>>>(Wfx, wfxhi, wfxlo, OO*DD/4);
    split_kernel<<<(OO*DD/4 + 255)/256, blk>>>(Wfn, wfnhi, wfnlo, OO*DD/4);
    split_kernel<<<(OO*EE/4 + 255)/256, blk>>>(Wfe, wfehi, wfelo, OO*EE/4);

    // ---- x_att chain on tensor cores ----
    wgemm2<true, true, false, true><<<dim3(HH/128, NN/128), blk, WG2_SMEM>>>(
        xhi, xlo, w1xhi, w1xlo, nullptr, nullptr, h1hi, h1lo, HH, DD, HH, 0);
    wgemm2<true, false, false, true><<<dim3(HH/128, NN/128), blk, WG2_SMEM>>>(
        h1hi, h1lo, w2xhi, w2xlo, nullptr, nullptr, xahi, xalo, HH, HH, HH, 0);
    wgemm2<false, false, false, false><<<dim3(HH/128, NN/128), blk, WG2_SMEM>>>(
        xahi, xalo, w2nhi, w2nlo, nullptr, yn, nullptr, nullptr, HH, HH, HH, 0);
    wgemm2<false, false, false, false><<<dim3(HH/128, NN/128), blk, WG2_SMEM>>>(
        xahi, xalo, w2ehi, w2elo, nullptr, ye, nullptr, nullptr, HH, HH, HH, 0);

    // ---- attention logits (small-stage cp.async pipeline, 2 CTAs/SM) ----
    ws_mma<DD><<<(NN * KNB) / 128, blk, WS5_SMEM>>>(nhi, nlo, w1nhi, w1nlo, yn, wsn);
    ws_mma<EE><<<(NN * KNB) / 128, blk, WS5_SMEM>>>(ehi, elo, w1ehi, w1elo, ye, wse);

    // ---- softmax + aggregation ----
    softmax_agg<<<NN, 128>>>(wsn, wse, mask, neibs, edge, aggn, agge);

    // ---- output GEMMs on tensor cores ----
    split_kernel<<<(NN*DD/4 + 255)/256, blk>>>(aggn, anhi, anlo, NN*DD/4);
    split_kernel<<<(NN*EE/4 + 255)/256, blk>>>(agge, aehi, aelo, NN*EE/4);

    wgemm2<true, false, true, false><<<dim3(OO/128, NN/128), blk, WG2_SMEM>>>(
        xhi, xlo, wfxhi, wfxlo, bfx, out, nullptr, nullptr, OO, DD, 3*OO, 0);
    wgemm2<true, false, true, false><<<dim3(OO/128, NN/128), blk, WG2_SMEM>>>(
        anhi, anlo, wfnhi, wfnlo, bfn, out, nullptr, nullptr, OO, DD, 3*OO, OO);
    wgemm2<true, false, true, false><<<dim3(OO/128, NN/128), blk, WG2_SMEM>>>(
        aehi, aelo, wfehi, wfelo, bfe, out, nullptr, nullptr, OO, EE, 3*OO, 2*OO);
}